// round 3
// baseline (speedup 1.0000x reference)
#include <cuda_runtime.h>
#include <math.h>

// Problem constants
#define Bn   16
#define Cc   256
#define HWn  4096
#define NHh  4
#define HDd  64
#define CHW  1048576L   // C*HW
#define NSPL 8          // n-split slabs for attention scores

// ---------------- scratch (static __device__ — no allocation allowed) ----------------
__device__ float g_q[16777216];      // (B,256,HW)
__device__ float g_kv[67108864];     // (2B,512,HW)
__device__ float g_attn[16777216];   // (B,256,HW)
__device__ float g_x[16777216];      // residual mid
__device__ float g_y1[16777216];
__device__ float g_y2[16777216];
__device__ float g_S[NSPL*64*64*128];   // score partials [slab][bh][c][dd]
__device__ float g_qn2[NSPL*64*64];
__device__ float g_kn2[NSPL*64*128];
__device__ float g_P[64*64*128];        // gated softmax probs [bh][c][dd]
__device__ float g_muq[65536],  g_rsq[65536];
__device__ float g_mukv[131072],g_rskv[131072];
__device__ float g_mux[65536],  g_rsx[65536];
__device__ float g_Wq[65536],  g_Sq[256],  g_Bq[256];
__device__ float g_Wkv[131072],g_Skv[512], g_Bkv[512];
__device__ float g_Wf1[65536], g_Sf1[256], g_Bf1[256];

// ---------------- weight fold: W' = W*lnw, S=sum(W'), b2=sum(W*lnb) ----------------
__global__ void prep_w(const float* __restrict__ qw,  const float* __restrict__ qlw,  const float* __restrict__ qlb,
                       const float* __restrict__ kvw, const float* __restrict__ kvlw, const float* __restrict__ kvlb,
                       const float* __restrict__ f1w, const float* __restrict__ flw,  const float* __restrict__ flb)
{
    int row = blockIdx.x;  // 0..1023
    const float *W, *lw, *lb; float *Wo, *So, *Bo; int o;
    if (row < 256)      { W=qw;  lw=qlw;  lb=qlb;  Wo=g_Wq;  So=g_Sq;  Bo=g_Bq;  o=row;     }
    else if (row < 768) { W=kvw; lw=kvlw; lb=kvlb; Wo=g_Wkv; So=g_Skv; Bo=g_Bkv; o=row-256; }
    else                { W=f1w; lw=flw;  lb=flb;  Wo=g_Wf1; So=g_Sf1; Bo=g_Bf1; o=row-768; }
    int c = threadIdx.x;
    float w  = W[o*256 + c];
    float wp = w * lw[c];
    Wo[o*256 + c] = wp;
    float bb = w * lb[c];
    __shared__ float r1[256], r2[256];
    r1[c] = wp; r2[c] = bb;
    __syncthreads();
    for (int s = 128; s > 0; s >>= 1) {
        if (c < s) { r1[c] += r1[c+s]; r2[c] += r2[c+s]; }
        __syncthreads();
    }
    if (c == 0) { So[o] = r1[0]; Bo[o] = r2[0]; }
}

// ---------------- per-pixel LN stats (mean over C=256 channels) ----------------
__global__ void __launch_bounds__(256) ln_stats(const float* __restrict__ x,
                                                float* __restrict__ mu, float* __restrict__ rstd)
{
    __shared__ float s1[4][64], s2[4][64];
    int tid = threadIdx.x;
    int pl  = tid & 63, cg = tid >> 6;           // 64 pixels/block, 4 channel groups
    long pix = (long)blockIdx.x * 64 + pl;
    int b = (int)(pix >> 12);
    int n = (int)(pix & 4095);
    const float* xp = x + (long)b*CHW + n;
    float a = 0.f, a2 = 0.f;
    #pragma unroll 8
    for (int c = cg*64; c < cg*64 + 64; c++) { float v = xp[(long)c*HWn]; a += v; a2 += v*v; }
    s1[cg][pl] = a; s2[cg][pl] = a2;
    __syncthreads();
    if (tid < 64) {
        float t1 = s1[0][tid]+s1[1][tid]+s1[2][tid]+s1[3][tid];
        float t2 = s2[0][tid]+s2[1][tid]+s2[2][tid]+s2[3][tid];
        float m   = t1 * (1.0f/256.0f);
        float var = t2 * (1.0f/256.0f) - m*m;
        long p = (long)blockIdx.x*64 + tid;
        mu[p]   = m;
        rstd[p] = rsqrtf(fmaxf(var, 0.0f) + 1e-6f);
    }
}

// ---------------- generic 128x128x(K=256) SGEMM with LN-fold / bias / residual epilogue ----------------
// out[bz][m][n] = epilogue( sum_c A[m][c] * X[bz][c][n] )
__global__ void __launch_bounds__(256,2) gemm128(
    const float* __restrict__ A,
    const float* __restrict__ X0, const float* __restrict__ X1, int split, long sX,
    float* __restrict__ Out, long sOut,
    const float* __restrict__ mu, const float* __restrict__ rstd,    // LN fold (per bz*HW+n)
    const float* __restrict__ Srow, const float* __restrict__ bias2, // LN fold (per m)
    const float* __restrict__ bias,                                  // plain bias (per m)
    const float* __restrict__ Res, long sRes)                        // residual (per bz,m,n)
{
    int bz = blockIdx.z;
    const float* X   = (bz < split) ? X0 + (long)bz*sX : X1 + (long)(bz-split)*sX;
    float*       out = Out + (long)bz*sOut;
    const float* res = Res ? Res + (long)bz*sRes : (const float*)0;
    int n0 = blockIdx.x * 128, m0 = blockIdx.y * 128;

    __shared__ float As[16][128];
    __shared__ float Bs[16][128];
    int tid = threadIdx.x;
    int tx = tid & 15, ty = tid >> 4;
    int arow = tid >> 2, akq = (tid & 3) << 2;
    int brow = tid >> 5, bcol = (tid & 31) << 2;

    float acc[8][8];
    #pragma unroll
    for (int i = 0; i < 8; i++)
        #pragma unroll
        for (int j = 0; j < 8; j++) acc[i][j] = 0.f;

    for (int k0 = 0; k0 < 256; k0 += 16) {
        float4 a0 = *(const float4*)&A[(long)(m0+arow   )*256 + k0 + akq];
        float4 a1 = *(const float4*)&A[(long)(m0+arow+64)*256 + k0 + akq];
        float4 b0 = *(const float4*)&X[(long)(k0+brow  )*HWn + n0 + bcol];
        float4 b1 = *(const float4*)&X[(long)(k0+brow+8)*HWn + n0 + bcol];
        As[akq+0][arow]=a0.x; As[akq+1][arow]=a0.y; As[akq+2][arow]=a0.z; As[akq+3][arow]=a0.w;
        As[akq+0][arow+64]=a1.x; As[akq+1][arow+64]=a1.y; As[akq+2][arow+64]=a1.z; As[akq+3][arow+64]=a1.w;
        *(float4*)&Bs[brow  ][bcol] = b0;
        *(float4*)&Bs[brow+8][bcol] = b1;
        __syncthreads();
        #pragma unroll
        for (int k = 0; k < 16; k++) {
            float4 pa0 = *(const float4*)&As[k][ty*4];
            float4 pa1 = *(const float4*)&As[k][ty*4+64];
            float4 pb0 = *(const float4*)&Bs[k][tx*4];
            float4 pb1 = *(const float4*)&Bs[k][tx*4+64];
            float av[8] = {pa0.x,pa0.y,pa0.z,pa0.w, pa1.x,pa1.y,pa1.z,pa1.w};
            float bv[8] = {pb0.x,pb0.y,pb0.z,pb0.w, pb1.x,pb1.y,pb1.z,pb1.w};
            #pragma unroll
            for (int i = 0; i < 8; i++)
                #pragma unroll
                for (int j = 0; j < 8; j++) acc[i][j] = fmaf(av[i], bv[j], acc[i][j]);
        }
        __syncthreads();
    }

    float muv[8], rsv[8];
    if (mu) {
        #pragma unroll
        for (int j = 0; j < 8; j++) {
            int n = n0 + tx*4 + (j < 4 ? j : 60 + j);
            long p = (long)bz*HWn + n;
            muv[j] = mu[p]; rsv[j] = rstd[p];
        }
    }
    #pragma unroll
    for (int i = 0; i < 8; i++) {
        int m = m0 + ty*4 + (i < 4 ? i : 60 + i);
        float sr = 0.f, b2 = 0.f;
        if (mu)       { sr = Srow[m]; b2 = bias2[m]; }
        else if (bias){ b2 = bias[m]; }
        #pragma unroll
        for (int j = 0; j < 8; j++) {
            int n = n0 + tx*4 + (j < 4 ? j : 60 + j);
            float v = acc[i][j];
            if (mu) v = rsv[j]*(v - muv[j]*sr) + b2;
            else    { v += b2; if (res) v += res[(long)m*HWn + n]; }
            out[(long)m*HWn + n] = v;
        }
    }
}

// ---------------- attention A1: raw scores Q*[Ktex;Kdep]^T partials + row norms ----------------
__global__ void __launch_bounds__(256) attn_scores()
{
    int slab = blockIdx.x;      // 0..7 (n-split)
    int bh   = blockIdx.y;      // 0..63
    int b = bh >> 2, h = bh & 3;
    __shared__ float Qt[32][68];       // [n][c]
    __shared__ float Kt[32][132];      // [n][dd]
    __shared__ const float* krow[128];
    int tid = threadIdx.x;
    if (tid < 128) {
        int dd = tid;
        krow[dd] = (dd < 64)
            ? g_kv + ((long)b*512       + h*64 + dd      ) * HWn
            : g_kv + ((long)(b+16)*512  + h*64 + (dd-64) ) * HWn;
    }
    const float* Q = g_q + ((long)b*256 + h*64) * HWn;
    __syncthreads();
    int tx = tid & 15, ty = tid >> 4;
    float acc[4][8];
    #pragma unroll
    for (int i = 0; i < 4; i++)
        #pragma unroll
        for (int j = 0; j < 8; j++) acc[i][j] = 0.f;
    float qn = 0.f, kn = 0.f;
    int n0 = slab * 512;

    for (int nc = n0; nc < n0 + 512; nc += 32) {
        for (int i = tid; i < 64*8; i += 256) {
            int c = i >> 3, q = i & 7;
            float4 v = *(const float4*)(Q + (long)c*HWn + nc + q*4);
            Qt[q*4+0][c]=v.x; Qt[q*4+1][c]=v.y; Qt[q*4+2][c]=v.z; Qt[q*4+3][c]=v.w;
        }
        for (int i = tid; i < 128*8; i += 256) {
            int dd = i >> 3, q = i & 7;
            float4 v = *(const float4*)(krow[dd] + nc + q*4);
            Kt[q*4+0][dd]=v.x; Kt[q*4+1][dd]=v.y; Kt[q*4+2][dd]=v.z; Kt[q*4+3][dd]=v.w;
        }
        __syncthreads();
        if (tid < 64) {
            int c = tid;
            #pragma unroll
            for (int k = 0; k < 32; k++) { float v = Qt[k][c]; qn = fmaf(v, v, qn); }
        } else if (tid < 192) {
            int dd = tid - 64;
            #pragma unroll
            for (int k = 0; k < 32; k++) { float v = Kt[k][dd]; kn = fmaf(v, v, kn); }
        }
        #pragma unroll
        for (int k = 0; k < 32; k++) {
            float4 a  = *(const float4*)&Qt[k][ty*4];
            float4 b0 = *(const float4*)&Kt[k][tx*8];
            float4 b1 = *(const float4*)&Kt[k][tx*8+4];
            float av[4] = {a.x,a.y,a.z,a.w};
            float bv[8] = {b0.x,b0.y,b0.z,b0.w, b1.x,b1.y,b1.z,b1.w};
            #pragma unroll
            for (int i = 0; i < 4; i++)
                #pragma unroll
                for (int j = 0; j < 8; j++) acc[i][j] = fmaf(av[i], bv[j], acc[i][j]);
        }
        __syncthreads();
    }
    long base = (long)slab*64 + bh;
    float* Sp = g_S + base*64*128;
    #pragma unroll
    for (int i = 0; i < 4; i++)
        #pragma unroll
        for (int j = 0; j < 8; j++)
            Sp[(ty*4+i)*128 + tx*8 + j] = acc[i][j];
    if (tid < 64)       g_qn2[base*64  + tid]       = qn;
    else if (tid < 192) g_kn2[base*128 + (tid-64)]  = kn;
}

// ---------------- attention A2: combine partials, normalize, softmax, fold gate ----------------
__global__ void __launch_bounds__(128) attn_softmax(const float* __restrict__ attn_scale)
{
    int bh = blockIdx.x; int h = bh & 3;
    __shared__ float qn[64], kn[128];
    int tid = threadIdx.x;
    if (tid < 64) {
        float s = 0.f;
        for (int sl = 0; sl < NSPL; sl++) s += g_qn2[((long)sl*64 + bh)*64 + tid];
        qn[tid] = fmaxf(sqrtf(s), 1e-12f);
    }
    {
        float s = 0.f;
        for (int sl = 0; sl < NSPL; sl++) s += g_kn2[((long)sl*64 + bh)*128 + tid];
        kn[tid] = fmaxf(sqrtf(s), 1e-12f);
    }
    __syncthreads();
    int c = tid & 63, half = tid >> 6;
    float v[64];
    const float* Sp = g_S + (long)bh*64*128 + c*128 + half*64;
    float iq = 1.0f / qn[c];
    #pragma unroll
    for (int d = 0; d < 64; d++) {
        float s = 0.f;
        for (int sl = 0; sl < NSPL; sl++) s += Sp[(long)sl*64*64*128 + d];
        v[d] = s * iq / kn[half*64 + d];
    }
    float mx = -1e30f;
    #pragma unroll
    for (int d = 0; d < 64; d++) mx = fmaxf(mx, v[d]);
    float sum = 0.f;
    #pragma unroll
    for (int d = 0; d < 64; d++) { v[d] = expf(v[d] - mx); sum += v[d]; }
    float g   = 1.0f / (1.0f + expf(-attn_scale[h]));
    float fac = (half == 0 ? g : 1.0f - g) / sum;
    float* P = g_P + (long)bh*64*128 + c*128 + half*64;
    #pragma unroll
    for (int d = 0; d < 64; d++) P[d] = v[d] * fac;
}

// ---------------- attention A3: O = P_comb(64x128) * [Vtex;Vdep](128xHW) ----------------
__global__ void __launch_bounds__(256) attn_pv()
{
    int nt = blockIdx.x;   // 0..31 (128 cols each)
    int bh = blockIdx.y;
    int b = bh >> 2, h = bh & 3;
    __shared__ float Pt[128][68];   // [dd][c]
    __shared__ float Vs[16][132];   // [dd_chunk][n]
    __shared__ const float* vrow[128];
    int tid = threadIdx.x;
    if (tid < 128) {
        int dd = tid;
        vrow[dd] = (dd < 64)
            ? g_kv + ((long)b*512      + 256 + h*64 + dd      ) * HWn
            : g_kv + ((long)(b+16)*512 + 256 + h*64 + (dd-64) ) * HWn;
    }
    const float* P = g_P + (long)bh*64*128;
    for (int i = tid; i < 64*128; i += 256) {
        int c = i >> 7, dd = i & 127;
        Pt[dd][c] = P[i];
    }
    __syncthreads();
    int tx = tid & 15, ty = tid >> 4;
    float acc[4][8];
    #pragma unroll
    for (int i = 0; i < 4; i++)
        #pragma unroll
        for (int j = 0; j < 8; j++) acc[i][j] = 0.f;
    int n0 = nt * 128;
    for (int d0 = 0; d0 < 128; d0 += 16) {
        for (int i = tid; i < 16*32; i += 256) {
            int dd = i >> 5, q = i & 31;
            *(float4*)&Vs[dd][q*4] = *(const float4*)(vrow[d0+dd] + n0 + q*4);
        }
        __syncthreads();
        #pragma unroll
        for (int k = 0; k < 16; k++) {
            float4 a  = *(const float4*)&Pt[d0+k][ty*4];
            float4 b0 = *(const float4*)&Vs[k][tx*8];
            float4 b1 = *(const float4*)&Vs[k][tx*8+4];
            float av[4] = {a.x,a.y,a.z,a.w};
            float bv[8] = {b0.x,b0.y,b0.z,b0.w, b1.x,b1.y,b1.z,b1.w};
            #pragma unroll
            for (int i = 0; i < 4; i++)
                #pragma unroll
                for (int j = 0; j < 8; j++) acc[i][j] = fmaf(av[i], bv[j], acc[i][j]);
        }
        __syncthreads();
    }
    float* O = g_attn + ((long)b*256 + h*64) * HWn;
    #pragma unroll
    for (int i = 0; i < 4; i++) {
        float4 o0 = make_float4(acc[i][0],acc[i][1],acc[i][2],acc[i][3]);
        float4 o1 = make_float4(acc[i][4],acc[i][5],acc[i][6],acc[i][7]);
        *(float4*)(O + (long)(ty*4+i)*HWn + n0 + tx*8    ) = o0;
        *(float4*)(O + (long)(ty*4+i)*HWn + n0 + tx*8 + 4) = o1;
    }
}

// ---------------- depthwise 3x3 SAME + exact GELU ----------------
__global__ void dwconv_gelu(const float* __restrict__ dww)
{
    int bc = blockIdx.x;         // b*256 + c
    int c  = bc & 255;
    int hh = blockIdx.y * 4 + threadIdx.y;
    int tx = threadIdx.x;        // w in 0..63
    const float* in = g_y1 + (long)bc * HWn;
    float s = 0.f;
    #pragma unroll
    for (int di = -1; di <= 1; di++) {
        int hi = hh + di;
        if (hi < 0 || hi > 63) continue;
        #pragma unroll
        for (int dj = -1; dj <= 1; dj++) {
            int wj = tx + dj;
            if (wj < 0 || wj > 63) continue;
            s = fmaf(in[hi*64 + wj], dww[c*9 + (di+1)*3 + (dj+1)], s);
        }
    }
    float g = 0.5f * s * (1.0f + erff(s * 0.70710678118654752f));
    g_y2[(long)bc * HWn + hh*64 + tx] = g;
}

// ---------------- launch ----------------
extern "C" void kernel_launch(void* const* d_in, const int* in_sizes, int n_in,
                              void* d_out, int out_size)
{
    const float* img    = (const float*)d_in[0];
    const float* tex    = (const float*)d_in[1];
    const float* dep    = (const float*)d_in[2];
    const float* qnw    = (const float*)d_in[3];
    const float* qnb    = (const float*)d_in[4];
    const float* kvnw   = (const float*)d_in[5];
    const float* kvnb   = (const float*)d_in[6];
    const float* ascale = (const float*)d_in[7];
    const float* qpw    = (const float*)d_in[8];
    const float* kvpw   = (const float*)d_in[9];
    const float* opw    = (const float*)d_in[10];
    const float* opb    = (const float*)d_in[11];
    const float* fnw    = (const float*)d_in[12];
    const float* fnb    = (const float*)d_in[13];
    const float* f1w    = (const float*)d_in[14];
    const float* dww    = (const float*)d_in[15];
    const float* f2w    = (const float*)d_in[16];
    float* outp = (float*)d_out;

    float *p_q,*p_kv,*p_attn,*p_x,*p_y1,*p_y2;
    float *p_muq,*p_rsq,*p_mukv,*p_rskv,*p_mux,*p_rsx;
    float *p_Wq,*p_Sq,*p_Bq,*p_Wkv,*p_Skv,*p_Bkv,*p_Wf1,*p_Sf1,*p_Bf1;
    cudaGetSymbolAddress((void**)&p_q,    g_q);
    cudaGetSymbolAddress((void**)&p_kv,   g_kv);
    cudaGetSymbolAddress((void**)&p_attn, g_attn);
    cudaGetSymbolAddress((void**)&p_x,    g_x);
    cudaGetSymbolAddress((void**)&p_y1,   g_y1);
    cudaGetSymbolAddress((void**)&p_y2,   g_y2);
    cudaGetSymbolAddress((void**)&p_muq,  g_muq);
    cudaGetSymbolAddress((void**)&p_rsq,  g_rsq);
    cudaGetSymbolAddress((void**)&p_mukv, g_mukv);
    cudaGetSymbolAddress((void**)&p_rskv, g_rskv);
    cudaGetSymbolAddress((void**)&p_mux,  g_mux);
    cudaGetSymbolAddress((void**)&p_rsx,  g_rsx);
    cudaGetSymbolAddress((void**)&p_Wq,   g_Wq);
    cudaGetSymbolAddress((void**)&p_Sq,   g_Sq);
    cudaGetSymbolAddress((void**)&p_Bq,   g_Bq);
    cudaGetSymbolAddress((void**)&p_Wkv,  g_Wkv);
    cudaGetSymbolAddress((void**)&p_Skv,  g_Skv);
    cudaGetSymbolAddress((void**)&p_Bkv,  g_Bkv);
    cudaGetSymbolAddress((void**)&p_Wf1,  g_Wf1);
    cudaGetSymbolAddress((void**)&p_Sf1,  g_Sf1);
    cudaGetSymbolAddress((void**)&p_Bf1,  g_Bf1);

    // 0) fold LN weights into GEMM weights
    prep_w<<<1024, 256>>>(qpw,qnw,qnb, kvpw,kvnw,kvnb, f1w,fnw,fnb);
    // 1) LN stats
    ln_stats<<<1024, 256>>>(img, p_muq,  p_rsq);
    ln_stats<<<1024, 256>>>(tex, p_mukv, p_rskv);
    ln_stats<<<1024, 256>>>(dep, p_mukv + 65536, p_rskv + 65536);
    // 2) q = Wq' @ img  (LN folded in epilogue)
    gemm128<<<dim3(32,2,16), 256>>>(p_Wq, img, img, 99, CHW, p_q, CHW,
                                    p_muq, p_rsq, p_Sq, p_Bq, nullptr, nullptr, 0);
    // 3) kv = Wkv' @ [tex;dep]
    gemm128<<<dim3(32,4,32), 256>>>(p_Wkv, tex, dep, 16, CHW, p_kv, 512L*HWn,
                                    p_mukv, p_rskv, p_Skv, p_Bkv, nullptr, nullptr, 0);
    // 4) attention
    attn_scores <<<dim3(NSPL,64), 256>>>();
    attn_softmax<<<64, 128>>>(ascale);
    attn_pv     <<<dim3(32,64), 256>>>();
    // 5) x = img + Wo @ attn + bias
    gemm128<<<dim3(32,2,16), 256>>>(opw, p_attn, p_attn, 99, CHW, p_x, CHW,
                                    nullptr, nullptr, nullptr, nullptr, opb, img, CHW);
    // 6) ffn
    ln_stats<<<1024, 256>>>(p_x, p_mux, p_rsx);
    gemm128<<<dim3(32,2,16), 256>>>(p_Wf1, p_x, p_x, 99, CHW, p_y1, CHW,
                                    p_mux, p_rsx, p_Sf1, p_Bf1, nullptr, nullptr, 0);
    dwconv_gelu<<<dim3(4096,16), dim3(64,4)>>>(dww);
    // 7) out = x + fc2 @ y2
    gemm128<<<dim3(32,2,16), 256>>>(f2w, p_y2, p_y2, 99, CHW, outp, CHW,
                                    nullptr, nullptr, nullptr, nullptr, nullptr, p_x, CHW);
}

// round 4
// speedup vs baseline: 2.1207x; 2.1207x over previous
#include <cuda_runtime.h>
#include <math.h>

// Problem constants
#define Bn   16
#define Cc   256
#define HWn  4096
#define NHh  4
#define HDd  64
#define CHW  1048576L   // C*HW
#define NSPL 8          // n-split slabs for attention scores

// ---------------- scratch (static __device__ — no allocation allowed) ----------------
__device__ float g_q[16777216];      // (B,256,HW)
__device__ float g_kv[67108864];     // (2B,512,HW)
__device__ float g_attn[16777216];   // (B,256,HW)
__device__ float g_x[16777216];      // residual mid
__device__ float g_y1[16777216];
__device__ float g_y2[16777216];
__device__ float g_S[NSPL*64*64*128];   // score partials [slab][bh][c][dd]
__device__ float g_qn2[NSPL*64*64];
__device__ float g_kn2[NSPL*64*128];
__device__ float g_P[64*64*128];        // gated softmax probs [bh][c][dd]
__device__ float g_muq[65536],  g_rsq[65536];
__device__ float g_mukv[131072],g_rskv[131072];
__device__ float g_mux[65536],  g_rsx[65536];
__device__ float g_Wq[65536],  g_Sq[256],  g_Bq[256];
__device__ float g_Wkv[131072],g_Skv[512], g_Bkv[512];
__device__ float g_Wf1[65536], g_Sf1[256], g_Bf1[256];

// ---------------- tf32 helpers ----------------
__device__ __forceinline__ void mma_tf32(float* c, const unsigned* a, unsigned b0, unsigned b1)
{
    asm volatile(
        "mma.sync.aligned.m16n8k8.row.col.f32.tf32.tf32.f32 "
        "{%0,%1,%2,%3},{%4,%5,%6,%7},{%8,%9},{%0,%1,%2,%3};\n"
        : "+f"(c[0]), "+f"(c[1]), "+f"(c[2]), "+f"(c[3])
        : "r"(a[0]), "r"(a[1]), "r"(a[2]), "r"(a[3]), "r"(b0), "r"(b1));
}
__device__ __forceinline__ void split_tf32(float f, unsigned& hi, unsigned& lo)
{
    unsigned u = __float_as_uint(f) & 0xffffe000u;
    hi = u;
    float l = f - __uint_as_float(u);
    lo = __float_as_uint(l) & 0xffffe000u;
}

// ---------------- weight fold: W' = W*lnw, S=sum(W'), b2=sum(W*lnb) ----------------
__global__ void prep_w(const float* __restrict__ qw,  const float* __restrict__ qlw,  const float* __restrict__ qlb,
                       const float* __restrict__ kvw, const float* __restrict__ kvlw, const float* __restrict__ kvlb,
                       const float* __restrict__ f1w, const float* __restrict__ flw,  const float* __restrict__ flb)
{
    int row = blockIdx.x;  // 0..1023
    const float *W, *lw, *lb; float *Wo, *So, *Bo; int o;
    if (row < 256)      { W=qw;  lw=qlw;  lb=qlb;  Wo=g_Wq;  So=g_Sq;  Bo=g_Bq;  o=row;     }
    else if (row < 768) { W=kvw; lw=kvlw; lb=kvlb; Wo=g_Wkv; So=g_Skv; Bo=g_Bkv; o=row-256; }
    else                { W=f1w; lw=flw;  lb=flb;  Wo=g_Wf1; So=g_Sf1; Bo=g_Bf1; o=row-768; }
    int c = threadIdx.x;
    float w  = W[o*256 + c];
    float wp = w * lw[c];
    Wo[o*256 + c] = wp;
    float bb = w * lb[c];
    __shared__ float r1[256], r2[256];
    r1[c] = wp; r2[c] = bb;
    __syncthreads();
    for (int s = 128; s > 0; s >>= 1) {
        if (c < s) { r1[c] += r1[c+s]; r2[c] += r2[c+s]; }
        __syncthreads();
    }
    if (c == 0) { So[o] = r1[0]; Bo[o] = r2[0]; }
}

// ---------------- per-pixel LN stats (mean over C=256 channels) ----------------
__global__ void __launch_bounds__(256) ln_stats(const float* __restrict__ x,
                                                float* __restrict__ mu, float* __restrict__ rstd)
{
    __shared__ float s1[4][64], s2[4][64];
    int tid = threadIdx.x;
    int pl  = tid & 63, cg = tid >> 6;
    long pix = (long)blockIdx.x * 64 + pl;
    int b = (int)(pix >> 12);
    int n = (int)(pix & 4095);
    const float* xp = x + (long)b*CHW + n;
    float a = 0.f, a2 = 0.f;
    #pragma unroll 8
    for (int c = cg*64; c < cg*64 + 64; c++) { float v = xp[(long)c*HWn]; a += v; a2 += v*v; }
    s1[cg][pl] = a; s2[cg][pl] = a2;
    __syncthreads();
    if (tid < 64) {
        float t1 = s1[0][tid]+s1[1][tid]+s1[2][tid]+s1[3][tid];
        float t2 = s2[0][tid]+s2[1][tid]+s2[2][tid]+s2[3][tid];
        float m   = t1 * (1.0f/256.0f);
        float var = t2 * (1.0f/256.0f) - m*m;
        long p = (long)blockIdx.x*64 + tid;
        mu[p]   = m;
        rstd[p] = rsqrtf(fmaxf(var, 0.0f) + 1e-6f);
    }
}

// ---------------- tensor-core 128x128x256 GEMM (3xTF32) with epilogues ----------------
// out[bz][m][n] = epilogue( sum_c A[m][c] * X[bz][c][n] )
__global__ void __launch_bounds__(256) gemm_tc(
    const float* __restrict__ A,
    const float* __restrict__ X0, const float* __restrict__ X1, int split, long sX,
    float* __restrict__ Out, long sOut,
    const float* __restrict__ mu, const float* __restrict__ rstd,    // LN fold (per bz*HW+n)
    const float* __restrict__ Srow, const float* __restrict__ bias2, // LN fold (per m)
    const float* __restrict__ bias,                                  // plain bias (per m)
    const float* __restrict__ Res, long sRes)                        // residual
{
    int bz = blockIdx.z;
    const float* X   = (bz < split) ? X0 + (long)bz*sX : X1 + (long)(bz-split)*sX;
    float*       out = Out + (long)bz*sOut;
    const float* res = Res ? Res + (long)bz*sRes : (const float*)0;
    int n0 = blockIdx.x * 128, m0 = blockIdx.y * 128;

    __shared__ float As[16][136];   // [k][m], stride%32==8 -> conflict-free frag loads
    __shared__ float Bs[16][136];   // [k][n]
    int tid  = threadIdx.x;
    int lane = tid & 31, wid = tid >> 5;
    int g = lane >> 2, l4 = lane & 3;
    int wm = wid >> 1, wn = wid & 1;            // wm: 4x32 rows, wn: 2x64 cols
    int arow = tid >> 2, akq = (tid & 3) << 2;
    int brow = tid >> 5, bcol = (tid & 31) << 2;

    float acc[2][8][4];
    #pragma unroll
    for (int i = 0; i < 2; i++)
        #pragma unroll
        for (int j = 0; j < 8; j++)
            #pragma unroll
            for (int r = 0; r < 4; r++) acc[i][j][r] = 0.f;

    for (int k0 = 0; k0 < 256; k0 += 16) {
        float4 a0 = *(const float4*)&A[(long)(m0+arow   )*256 + k0 + akq];
        float4 a1 = *(const float4*)&A[(long)(m0+arow+64)*256 + k0 + akq];
        float4 b0 = *(const float4*)&X[(long)(k0+brow  )*HWn + n0 + bcol];
        float4 b1 = *(const float4*)&X[(long)(k0+brow+8)*HWn + n0 + bcol];
        As[akq+0][arow]=a0.x; As[akq+1][arow]=a0.y; As[akq+2][arow]=a0.z; As[akq+3][arow]=a0.w;
        As[akq+0][arow+64]=a1.x; As[akq+1][arow+64]=a1.y; As[akq+2][arow+64]=a1.z; As[akq+3][arow+64]=a1.w;
        *(float4*)&Bs[brow  ][bcol] = b0;
        *(float4*)&Bs[brow+8][bcol] = b1;
        __syncthreads();
        #pragma unroll
        for (int kk = 0; kk < 16; kk += 8) {
            unsigned ah[2][4], al[2][4];
            #pragma unroll
            for (int i = 0; i < 2; i++) {
                int row = wm*32 + i*16 + g;
                #pragma unroll
                for (int r = 0; r < 4; r++) {
                    float f = As[kk + l4 + ((r>>1)<<2)][row + ((r&1)<<3)];
                    split_tf32(f, ah[i][r], al[i][r]);
                }
            }
            #pragma unroll
            for (int j = 0; j < 8; j++) {
                int col = wn*64 + j*8 + g;
                unsigned bh0,bl0,bh1,bl1;
                split_tf32(Bs[kk+l4  ][col], bh0, bl0);
                split_tf32(Bs[kk+l4+4][col], bh1, bl1);
                #pragma unroll
                for (int i = 0; i < 2; i++) {
                    mma_tf32(acc[i][j], ah[i], bh0, bh1);
                    mma_tf32(acc[i][j], al[i], bh0, bh1);
                    mma_tf32(acc[i][j], ah[i], bl0, bl1);
                }
            }
        }
        __syncthreads();
    }

    #pragma unroll
    for (int i = 0; i < 2; i++) {
        #pragma unroll
        for (int h = 0; h < 2; h++) {
            int m = m0 + wm*32 + i*16 + g + h*8;
            float sr = 0.f, b2 = 0.f;
            if (mu)       { sr = Srow[m]; b2 = bias2[m]; }
            else if (bias){ b2 = bias[m]; }
            #pragma unroll
            for (int j = 0; j < 8; j++) {
                int n = n0 + wn*64 + j*8 + 2*l4;
                float v0 = acc[i][j][h*2+0], v1 = acc[i][j][h*2+1];
                if (mu) {
                    long p = (long)bz*HWn + n;
                    v0 = rstd[p  ]*(v0 - mu[p  ]*sr) + b2;
                    v1 = rstd[p+1]*(v1 - mu[p+1]*sr) + b2;
                } else {
                    v0 += b2; v1 += b2;
                    if (res) { v0 += res[(long)m*HWn + n]; v1 += res[(long)m*HWn + n + 1]; }
                }
                *(float2*)&out[(long)m*HWn + n] = make_float2(v0, v1);
            }
        }
    }
}

// ---------------- attention A1: raw scores Q*[Ktex;Kdep]^T partials + row norms ----------------
__global__ void __launch_bounds__(256) attn_scores()
{
    int slab = blockIdx.x;      // 0..7 (n-split)
    int bh   = blockIdx.y;      // 0..63
    int b = bh >> 2, h = bh & 3;
    __shared__ float Qt[32][72];        // [n(k)][c]
    __shared__ float Kt[32][136];       // [n(k)][dd]
    __shared__ const float* krow[128];
    int tid = threadIdx.x;
    if (tid < 128) {
        int dd = tid;
        krow[dd] = (dd < 64)
            ? g_kv + ((long)b*512       + h*64 + dd      ) * HWn
            : g_kv + ((long)(b+16)*512  + h*64 + (dd-64) ) * HWn;
    }
    const float* Q = g_q + ((long)b*256 + h*64) * HWn;
    __syncthreads();
    int lane = tid & 31, wid = tid >> 5;
    int g = lane >> 2, l4 = lane & 3;
    int wm = wid >> 2, wn = wid & 3;    // wm: 2x32 rows(c), wn: 4x32 cols(dd)
    float acc[2][4][4];
    #pragma unroll
    for (int i = 0; i < 2; i++)
        #pragma unroll
        for (int j = 0; j < 4; j++)
            #pragma unroll
            for (int r = 0; r < 4; r++) acc[i][j][r] = 0.f;
    float qn = 0.f, kn = 0.f;
    int n0 = slab * 512;

    for (int nc = n0; nc < n0 + 512; nc += 32) {
        for (int i = tid; i < 64*8; i += 256) {
            int c = i >> 3, q = i & 7;
            float4 v = *(const float4*)(Q + (long)c*HWn + nc + q*4);
            Qt[q*4+0][c]=v.x; Qt[q*4+1][c]=v.y; Qt[q*4+2][c]=v.z; Qt[q*4+3][c]=v.w;
        }
        for (int i = tid; i < 128*8; i += 256) {
            int dd = i >> 3, q = i & 7;
            float4 v = *(const float4*)(krow[dd] + nc + q*4);
            Kt[q*4+0][dd]=v.x; Kt[q*4+1][dd]=v.y; Kt[q*4+2][dd]=v.z; Kt[q*4+3][dd]=v.w;
        }
        __syncthreads();
        if (tid < 64) {
            int c = tid;
            #pragma unroll
            for (int k = 0; k < 32; k++) { float v = Qt[k][c]; qn = fmaf(v, v, qn); }
        } else if (tid < 192) {
            int dd = tid - 64;
            #pragma unroll
            for (int k = 0; k < 32; k++) { float v = Kt[k][dd]; kn = fmaf(v, v, kn); }
        }
        #pragma unroll
        for (int kk = 0; kk < 32; kk += 8) {
            unsigned ah[2][4], al[2][4];
            #pragma unroll
            for (int i = 0; i < 2; i++) {
                int row = wm*32 + i*16 + g;
                #pragma unroll
                for (int r = 0; r < 4; r++) {
                    float f = Qt[kk + l4 + ((r>>1)<<2)][row + ((r&1)<<3)];
                    split_tf32(f, ah[i][r], al[i][r]);
                }
            }
            #pragma unroll
            for (int j = 0; j < 4; j++) {
                int col = wn*32 + j*8 + g;
                unsigned bh0,bl0,bh1,bl1;
                split_tf32(Kt[kk+l4  ][col], bh0, bl0);
                split_tf32(Kt[kk+l4+4][col], bh1, bl1);
                #pragma unroll
                for (int i = 0; i < 2; i++) {
                    mma_tf32(acc[i][j], ah[i], bh0, bh1);
                    mma_tf32(acc[i][j], al[i], bh0, bh1);
                    mma_tf32(acc[i][j], ah[i], bl0, bl1);
                }
            }
        }
        __syncthreads();
    }
    long base = (long)slab*64 + bh;
    float* Sp = g_S + base*64*128;
    #pragma unroll
    for (int i = 0; i < 2; i++)
        #pragma unroll
        for (int h = 0; h < 2; h++) {
            int row = wm*32 + i*16 + g + h*8;
            #pragma unroll
            for (int j = 0; j < 4; j++) {
                int col = wn*32 + j*8 + 2*l4;
                *(float2*)&Sp[row*128 + col] = make_float2(acc[i][j][h*2], acc[i][j][h*2+1]);
            }
        }
    if (tid < 64)       g_qn2[base*64  + tid]       = qn;
    else if (tid < 192) g_kn2[base*128 + (tid-64)]  = kn;
}

// ---------------- attention A2: combine partials, normalize, softmax, fold gate ----------------
__global__ void __launch_bounds__(128) attn_softmax(const float* __restrict__ attn_scale)
{
    int bh = blockIdx.x; int h = bh & 3;
    __shared__ float qn[64], kn[128];
    int tid = threadIdx.x;
    if (tid < 64) {
        float s = 0.f;
        for (int sl = 0; sl < NSPL; sl++) s += g_qn2[((long)sl*64 + bh)*64 + tid];
        qn[tid] = fmaxf(sqrtf(s), 1e-12f);
    }
    {
        float s = 0.f;
        for (int sl = 0; sl < NSPL; sl++) s += g_kn2[((long)sl*64 + bh)*128 + tid];
        kn[tid] = fmaxf(sqrtf(s), 1e-12f);
    }
    __syncthreads();
    int c = tid & 63, half = tid >> 6;
    float v[64];
    const float* Sp = g_S + (long)bh*64*128 + c*128 + half*64;
    float iq = 1.0f / qn[c];
    #pragma unroll
    for (int d = 0; d < 64; d++) {
        float s = 0.f;
        for (int sl = 0; sl < NSPL; sl++) s += Sp[(long)sl*64*64*128 + d];
        v[d] = s * iq / kn[half*64 + d];
    }
    float mx = -1e30f;
    #pragma unroll
    for (int d = 0; d < 64; d++) mx = fmaxf(mx, v[d]);
    float sum = 0.f;
    #pragma unroll
    for (int d = 0; d < 64; d++) { v[d] = expf(v[d] - mx); sum += v[d]; }
    float gg  = 1.0f / (1.0f + expf(-attn_scale[h]));
    float fac = (half == 0 ? gg : 1.0f - gg) / sum;
    float* P = g_P + (long)bh*64*128 + c*128 + half*64;
    #pragma unroll
    for (int d = 0; d < 64; d++) P[d] = v[d] * fac;
}

// ---------------- attention A3: O = P_comb(64x128) * [Vtex;Vdep](128xHW) ----------------
__global__ void __launch_bounds__(256) attn_pv()
{
    int nt = blockIdx.x;   // 0..31 (128 cols each)
    int bh = blockIdx.y;
    int b = bh >> 2, h = bh & 3;
    __shared__ float Pt[128][72];    // [dd(k)][c]
    __shared__ float Vs[16][136];    // [dd chunk(k)][n]
    __shared__ const float* vrow[128];
    int tid = threadIdx.x;
    if (tid < 128) {
        int dd = tid;
        vrow[dd] = (dd < 64)
            ? g_kv + ((long)b*512      + 256 + h*64 + dd      ) * HWn
            : g_kv + ((long)(b+16)*512 + 256 + h*64 + (dd-64) ) * HWn;
    }
    const float* P = g_P + (long)bh*64*128;
    for (int i = tid; i < 64*128; i += 256) {
        int c = i >> 7, dd = i & 127;
        Pt[dd][c] = P[i];
    }
    __syncthreads();
    int lane = tid & 31, wid = tid >> 5;
    int g = lane >> 2, l4 = lane & 3;
    int wm = wid >> 2, wn = wid & 3;     // wm: 2x32 rows(c), wn: 4x32 cols(n)
    float acc[2][4][4];
    #pragma unroll
    for (int i = 0; i < 2; i++)
        #pragma unroll
        for (int j = 0; j < 4; j++)
            #pragma unroll
            for (int r = 0; r < 4; r++) acc[i][j][r] = 0.f;
    int n0 = nt * 128;
    for (int d0 = 0; d0 < 128; d0 += 16) {
        for (int i = tid; i < 16*32; i += 256) {
            int dd = i >> 5, q = i & 31;
            *(float4*)&Vs[dd][q*4] = *(const float4*)(vrow[d0+dd] + n0 + q*4);
        }
        __syncthreads();
        #pragma unroll
        for (int kk = 0; kk < 16; kk += 8) {
            unsigned ah[2][4], al[2][4];
            #pragma unroll
            for (int i = 0; i < 2; i++) {
                int row = wm*32 + i*16 + g;
                #pragma unroll
                for (int r = 0; r < 4; r++) {
                    float f = Pt[d0 + kk + l4 + ((r>>1)<<2)][row + ((r&1)<<3)];
                    split_tf32(f, ah[i][r], al[i][r]);
                }
            }
            #pragma unroll
            for (int j = 0; j < 4; j++) {
                int col = wn*32 + j*8 + g;
                unsigned bh0,bl0,bh1,bl1;
                split_tf32(Vs[kk+l4  ][col], bh0, bl0);
                split_tf32(Vs[kk+l4+4][col], bh1, bl1);
                #pragma unroll
                for (int i = 0; i < 2; i++) {
                    mma_tf32(acc[i][j], ah[i], bh0, bh1);
                    mma_tf32(acc[i][j], al[i], bh0, bh1);
                    mma_tf32(acc[i][j], ah[i], bl0, bl1);
                }
            }
        }
        __syncthreads();
    }
    float* O = g_attn + ((long)b*256 + h*64) * HWn;
    #pragma unroll
    for (int i = 0; i < 2; i++)
        #pragma unroll
        for (int h2 = 0; h2 < 2; h2++) {
            int row = wm*32 + i*16 + g + h2*8;
            #pragma unroll
            for (int j = 0; j < 4; j++) {
                int col = wn*32 + j*8 + 2*l4;
                *(float2*)(O + (long)row*HWn + n0 + col) =
                    make_float2(acc[i][j][h2*2], acc[i][j][h2*2+1]);
            }
        }
}

// ---------------- depthwise 3x3 SAME + exact GELU ----------------
__global__ void dwconv_gelu(const float* __restrict__ dww)
{
    int bc = blockIdx.x;         // b*256 + c
    int c  = bc & 255;
    int hh = blockIdx.y * 4 + threadIdx.y;
    int tx = threadIdx.x;        // w in 0..63
    const float* in = g_y1 + (long)bc * HWn;
    float s = 0.f;
    #pragma unroll
    for (int di = -1; di <= 1; di++) {
        int hi = hh + di;
        if (hi < 0 || hi > 63) continue;
        #pragma unroll
        for (int dj = -1; dj <= 1; dj++) {
            int wj = tx + dj;
            if (wj < 0 || wj > 63) continue;
            s = fmaf(in[hi*64 + wj], dww[c*9 + (di+1)*3 + (dj+1)], s);
        }
    }
    float g = 0.5f * s * (1.0f + erff(s * 0.70710678118654752f));
    g_y2[(long)bc * HWn + hh*64 + tx] = g;
}

// ---------------- launch ----------------
extern "C" void kernel_launch(void* const* d_in, const int* in_sizes, int n_in,
                              void* d_out, int out_size)
{
    const float* img    = (const float*)d_in[0];
    const float* tex    = (const float*)d_in[1];
    const float* dep    = (const float*)d_in[2];
    const float* qnw    = (const float*)d_in[3];
    const float* qnb    = (const float*)d_in[4];
    const float* kvnw   = (const float*)d_in[5];
    const float* kvnb   = (const float*)d_in[6];
    const float* ascale = (const float*)d_in[7];
    const float* qpw    = (const float*)d_in[8];
    const float* kvpw   = (const float*)d_in[9];
    const float* opw    = (const float*)d_in[10];
    const float* opb    = (const float*)d_in[11];
    const float* fnw    = (const float*)d_in[12];
    const float* fnb    = (const float*)d_in[13];
    const float* f1w    = (const float*)d_in[14];
    const float* dww    = (const float*)d_in[15];
    const float* f2w    = (const float*)d_in[16];
    float* outp = (float*)d_out;

    float *p_q,*p_kv,*p_attn,*p_x,*p_y1,*p_y2;
    float *p_muq,*p_rsq,*p_mukv,*p_rskv,*p_mux,*p_rsx;
    float *p_Wq,*p_Sq,*p_Bq,*p_Wkv,*p_Skv,*p_Bkv,*p_Wf1,*p_Sf1,*p_Bf1;
    cudaGetSymbolAddress((void**)&p_q,    g_q);
    cudaGetSymbolAddress((void**)&p_kv,   g_kv);
    cudaGetSymbolAddress((void**)&p_attn, g_attn);
    cudaGetSymbolAddress((void**)&p_x,    g_x);
    cudaGetSymbolAddress((void**)&p_y1,   g_y1);
    cudaGetSymbolAddress((void**)&p_y2,   g_y2);
    cudaGetSymbolAddress((void**)&p_muq,  g_muq);
    cudaGetSymbolAddress((void**)&p_rsq,  g_rsq);
    cudaGetSymbolAddress((void**)&p_mukv, g_mukv);
    cudaGetSymbolAddress((void**)&p_rskv, g_rskv);
    cudaGetSymbolAddress((void**)&p_mux,  g_mux);
    cudaGetSymbolAddress((void**)&p_rsx,  g_rsx);
    cudaGetSymbolAddress((void**)&p_Wq,   g_Wq);
    cudaGetSymbolAddress((void**)&p_Sq,   g_Sq);
    cudaGetSymbolAddress((void**)&p_Bq,   g_Bq);
    cudaGetSymbolAddress((void**)&p_Wkv,  g_Wkv);
    cudaGetSymbolAddress((void**)&p_Skv,  g_Skv);
    cudaGetSymbolAddress((void**)&p_Bkv,  g_Bkv);
    cudaGetSymbolAddress((void**)&p_Wf1,  g_Wf1);
    cudaGetSymbolAddress((void**)&p_Sf1,  g_Sf1);
    cudaGetSymbolAddress((void**)&p_Bf1,  g_Bf1);

    // 0) fold LN weights into GEMM weights
    prep_w<<<1024, 256>>>(qpw,qnw,qnb, kvpw,kvnw,kvnb, f1w,fnw,fnb);
    // 1) LN stats
    ln_stats<<<1024, 256>>>(img, p_muq,  p_rsq);
    ln_stats<<<1024, 256>>>(tex, p_mukv, p_rskv);
    ln_stats<<<1024, 256>>>(dep, p_mukv + 65536, p_rskv + 65536);
    // 2) q = Wq' @ img  (LN folded in epilogue)
    gemm_tc<<<dim3(32,2,16), 256>>>(p_Wq, img, img, 99, CHW, p_q, CHW,
                                    p_muq, p_rsq, p_Sq, p_Bq, nullptr, nullptr, 0);
    // 3) kv = Wkv' @ [tex;dep]
    gemm_tc<<<dim3(32,4,32), 256>>>(p_Wkv, tex, dep, 16, CHW, p_kv, 512L*HWn,
                                    p_mukv, p_rskv, p_Skv, p_Bkv, nullptr, nullptr, 0);
    // 4) attention
    attn_scores <<<dim3(NSPL,64), 256>>>();
    attn_softmax<<<64, 128>>>(ascale);
    attn_pv     <<<dim3(32,64), 256>>>();
    // 5) x = img + Wo @ attn + bias
    gemm_tc<<<dim3(32,2,16), 256>>>(opw, p_attn, p_attn, 99, CHW, p_x, CHW,
                                    nullptr, nullptr, nullptr, nullptr, opb, img, CHW);
    // 6) ffn
    ln_stats<<<1024, 256>>>(p_x, p_mux, p_rsx);
    gemm_tc<<<dim3(32,2,16), 256>>>(p_Wf1, p_x, p_x, 99, CHW, p_y1, CHW,
                                    p_mux, p_rsx, p_Sf1, p_Bf1, nullptr, nullptr, 0);
    dwconv_gelu<<<dim3(4096,16), dim3(64,4)>>>(dww);
    // 7) out = x + fc2 @ y2
    gemm_tc<<<dim3(32,2,16), 256>>>(f2w, p_y2, p_y2, 99, CHW, outp, CHW,
                                    nullptr, nullptr, nullptr, nullptr, nullptr, p_x, CHW);
}

// round 5
// speedup vs baseline: 3.0299x; 1.4287x over previous
#include <cuda_runtime.h>
#include <cuda_bf16.h>
#include <math.h>

// Problem constants
#define Bn   16
#define Cc   256
#define HWn  4096
#define NHh  4
#define HDd  64
#define CHW  1048576L   // C*HW
#define NSPL 8          // n-split slabs for attention scores

// ---------------- scratch (static __device__ — no allocation allowed) ----------------
__device__ float g_q[16777216];      // (B,256,HW)
__device__ float g_kv[67108864];     // (2B,512,HW)
__device__ float g_attn[16777216];   // (B,256,HW)
__device__ float g_x[16777216];      // residual mid
__device__ float g_y1[16777216];
__device__ float g_y2[16777216];
__device__ float g_S[NSPL*64*64*128];   // score partials [slab][bh][c][dd]
__device__ float g_qn2[NSPL*64*64];
__device__ float g_kn2[NSPL*64*128];
__device__ float g_P[64*64*128];        // gated softmax probs [bh][c][dd]
__device__ float g_muq[65536],  g_rsq[65536];
__device__ float g_mukv[131072],g_rskv[131072];
__device__ float g_mux[65536],  g_rsx[65536];
__device__ float g_Wq[65536],  g_Sq[256],  g_Bq[256];
__device__ float g_Wkv[131072],g_Skv[512], g_Bkv[512];
__device__ float g_Wf1[65536], g_Sf1[256], g_Bf1[256];

// ---------------- bf16 split helpers ----------------
// pack (x,y) k-pair into one 32-bit reg of 2 bf16: hi = RN(v), lo = RN(v - hi)
__device__ __forceinline__ void split2(float x, float y, unsigned &hi, unsigned &lo)
{
    __nv_bfloat162 h = __floats2bfloat162_rn(x, y);
    float rx = x - __low2float(h);
    float ry = y - __high2float(h);
    __nv_bfloat162 l = __floats2bfloat162_rn(rx, ry);
    hi = *reinterpret_cast<unsigned*>(&h);
    lo = *reinterpret_cast<unsigned*>(&l);
}
// mma.m16n8k16 bf16: same C-fragment layout as m16n8k8 tf32
__device__ __forceinline__ void mma_bf16(float* c, const unsigned* a, unsigned b0, unsigned b1)
{
    asm volatile(
        "mma.sync.aligned.m16n8k16.row.col.f32.bf16.bf16.f32 "
        "{%0,%1,%2,%3},{%4,%5,%6,%7},{%8,%9},{%0,%1,%2,%3};\n"
        : "+f"(c[0]), "+f"(c[1]), "+f"(c[2]), "+f"(c[3])
        : "r"(a[0]), "r"(a[1]), "r"(a[2]), "r"(a[3]), "r"(b0), "r"(b1));
}

// ---------------- weight fold: W' = W*lnw, S=sum(W'), b2=sum(W*lnb) ----------------
__global__ void prep_w(const float* __restrict__ qw,  const float* __restrict__ qlw,  const float* __restrict__ qlb,
                       const float* __restrict__ kvw, const float* __restrict__ kvlw, const float* __restrict__ kvlb,
                       const float* __restrict__ f1w, const float* __restrict__ flw,  const float* __restrict__ flb)
{
    int row = blockIdx.x;  // 0..1023
    const float *W, *lw, *lb; float *Wo, *So, *Bo; int o;
    if (row < 256)      { W=qw;  lw=qlw;  lb=qlb;  Wo=g_Wq;  So=g_Sq;  Bo=g_Bq;  o=row;     }
    else if (row < 768) { W=kvw; lw=kvlw; lb=kvlb; Wo=g_Wkv; So=g_Skv; Bo=g_Bkv; o=row-256; }
    else                { W=f1w; lw=flw;  lb=flb;  Wo=g_Wf1; So=g_Sf1; Bo=g_Bf1; o=row-768; }
    int c = threadIdx.x;
    float w  = W[o*256 + c];
    float wp = w * lw[c];
    Wo[o*256 + c] = wp;
    float bb = w * lb[c];
    __shared__ float r1[256], r2[256];
    r1[c] = wp; r2[c] = bb;
    __syncthreads();
    for (int s = 128; s > 0; s >>= 1) {
        if (c < s) { r1[c] += r1[c+s]; r2[c] += r2[c+s]; }
        __syncthreads();
    }
    if (c == 0) { So[o] = r1[0]; Bo[o] = r2[0]; }
}

// ---------------- per-pixel LN stats (mean over C=256 channels) ----------------
__global__ void __launch_bounds__(256) ln_stats(const float* __restrict__ x,
                                                float* __restrict__ mu, float* __restrict__ rstd)
{
    __shared__ float s1[4][64], s2[4][64];
    int tid = threadIdx.x;
    int pl  = tid & 63, cg = tid >> 6;
    long pix = (long)blockIdx.x * 64 + pl;
    int b = (int)(pix >> 12);
    int n = (int)(pix & 4095);
    const float* xp = x + (long)b*CHW + n;
    float a = 0.f, a2 = 0.f;
    #pragma unroll 8
    for (int c = cg*64; c < cg*64 + 64; c++) { float v = xp[(long)c*HWn]; a += v; a2 += v*v; }
    s1[cg][pl] = a; s2[cg][pl] = a2;
    __syncthreads();
    if (tid < 64) {
        float t1 = s1[0][tid]+s1[1][tid]+s1[2][tid]+s1[3][tid];
        float t2 = s2[0][tid]+s2[1][tid]+s2[2][tid]+s2[3][tid];
        float m   = t1 * (1.0f/256.0f);
        float var = t2 * (1.0f/256.0f) - m*m;
        long p = (long)blockIdx.x*64 + tid;
        mu[p]   = m;
        rstd[p] = rsqrtf(fmaxf(var, 0.0f) + 1e-6f);
    }
}

// ---------------- tensor-core 128x128x256 GEMM (3xBF16 split) with epilogues ----------------
// out[bz][m][n] = epilogue( sum_c A[m][c] * X[bz][c][n] )
__global__ void __launch_bounds__(256) gemm_tc(
    const float* __restrict__ A,
    const float* __restrict__ X0, const float* __restrict__ X1, int split, long sX,
    float* __restrict__ Out, long sOut,
    const float* __restrict__ mu, const float* __restrict__ rstd,    // LN fold (per bz*HW+n)
    const float* __restrict__ Srow, const float* __restrict__ bias2, // LN fold (per m)
    const float* __restrict__ bias,                                  // plain bias (per m)
    const float* __restrict__ Res, long sRes)                        // residual
{
    int bz = blockIdx.z;
    const float* X   = (bz < split) ? X0 + (long)bz*sX : X1 + (long)(bz-split)*sX;
    float*       out = Out + (long)bz*sOut;
    const float* res = Res ? Res + (long)bz*sRes : (const float*)0;
    int n0 = blockIdx.x * 128, m0 = blockIdx.y * 128;

    // packed bf16-pair tiles for one K-chunk of 16 (8 k-pairs)
    __shared__ unsigned Ahs[8][136], Als[8][136];  // [kp][m]  (136%32==8 -> conflict-free)
    __shared__ unsigned Bhs[8][136], Bls[8][136];  // [kp][n]
    int tid  = threadIdx.x;
    int lane = tid & 31, wid = tid >> 5;
    int g = lane >> 2, l4 = lane & 3;
    int wm = wid >> 1, wn = wid & 1;            // wm: 4x32 rows, wn: 2x64 cols

    int am  = tid >> 2;            // A staging: m (q adds 64)
    int akf = (tid & 3) << 2;      // k offset 0,4,8,12
    int bkp = tid >> 5, bng = (tid & 31) << 2;

    float acc[2][8][4];
    #pragma unroll
    for (int i = 0; i < 2; i++)
        #pragma unroll
        for (int j = 0; j < 8; j++)
            #pragma unroll
            for (int r = 0; r < 4; r++) acc[i][j][r] = 0.f;

    for (int k0 = 0; k0 < 256; k0 += 16) {
        // ---- stage A (128 x 16) ----
        #pragma unroll
        for (int q = 0; q < 2; q++) {
            int m = am + q*64;
            float4 v = *(const float4*)&A[(long)(m0+m)*256 + k0 + akf];
            unsigned h0,l0,h1,l1;
            split2(v.x, v.y, h0, l0);
            split2(v.z, v.w, h1, l1);
            int kp = akf >> 1;
            Ahs[kp][m] = h0; Als[kp][m] = l0;
            Ahs[kp+1][m] = h1; Als[kp+1][m] = l1;
        }
        // ---- stage B (16 x 128), pairs along k from two consecutive rows ----
        {
            const float* rp = &X[(long)(k0 + 2*bkp)*HWn + n0 + bng];
            float4 r0 = *(const float4*)rp;
            float4 r1 = *(const float4*)(rp + HWn);
            unsigned h0,l0,h1,l1,h2,l2,h3,l3;
            split2(r0.x, r1.x, h0, l0);
            split2(r0.y, r1.y, h1, l1);
            split2(r0.z, r1.z, h2, l2);
            split2(r0.w, r1.w, h3, l3);
            *(uint4*)&Bhs[bkp][bng] = make_uint4(h0,h1,h2,h3);
            *(uint4*)&Bls[bkp][bng] = make_uint4(l0,l1,l2,l3);
        }
        __syncthreads();
        // ---- fragments + MMA ----
        unsigned a_h[2][4], a_l[2][4];
        #pragma unroll
        for (int i = 0; i < 2; i++) {
            int row = wm*32 + i*16 + g;
            a_h[i][0]=Ahs[l4][row];   a_h[i][1]=Ahs[l4][row+8];
            a_h[i][2]=Ahs[l4+4][row]; a_h[i][3]=Ahs[l4+4][row+8];
            a_l[i][0]=Als[l4][row];   a_l[i][1]=Als[l4][row+8];
            a_l[i][2]=Als[l4+4][row]; a_l[i][3]=Als[l4+4][row+8];
        }
        #pragma unroll
        for (int j = 0; j < 8; j++) {
            int col = wn*64 + j*8 + g;
            unsigned bh0=Bhs[l4][col], bh1=Bhs[l4+4][col];
            unsigned bl0=Bls[l4][col], bl1=Bls[l4+4][col];
            #pragma unroll
            for (int i = 0; i < 2; i++) {
                mma_bf16(acc[i][j], a_h[i], bh0, bh1);
                mma_bf16(acc[i][j], a_l[i], bh0, bh1);
                mma_bf16(acc[i][j], a_h[i], bl0, bl1);
            }
        }
        __syncthreads();
    }

    #pragma unroll
    for (int i = 0; i < 2; i++) {
        #pragma unroll
        for (int h = 0; h < 2; h++) {
            int m = m0 + wm*32 + i*16 + g + h*8;
            float sr = 0.f, b2 = 0.f;
            if (mu)       { sr = Srow[m]; b2 = bias2[m]; }
            else if (bias){ b2 = bias[m]; }
            #pragma unroll
            for (int j = 0; j < 8; j++) {
                int n = n0 + wn*64 + j*8 + 2*l4;
                float v0 = acc[i][j][h*2+0], v1 = acc[i][j][h*2+1];
                if (mu) {
                    long p = (long)bz*HWn + n;
                    v0 = rstd[p  ]*(v0 - mu[p  ]*sr) + b2;
                    v1 = rstd[p+1]*(v1 - mu[p+1]*sr) + b2;
                } else {
                    v0 += b2; v1 += b2;
                    if (res) { v0 += res[(long)m*HWn + n]; v1 += res[(long)m*HWn + n + 1]; }
                }
                *(float2*)&out[(long)m*HWn + n] = make_float2(v0, v1);
            }
        }
    }
}

// ---------------- attention A1: raw scores Q*[Ktex;Kdep]^T partials + row norms ----------------
__global__ void __launch_bounds__(256) attn_scores()
{
    int slab = blockIdx.x;      // 0..7 (n-split)
    int bh   = blockIdx.y;      // 0..63
    int b = bh >> 2, h = bh & 3;
    __shared__ unsigned Qh[8][72],  Ql[8][72];    // [kp][c]
    __shared__ unsigned Kh[8][136], Kl[8][136];   // [kp][dd]
    int tid = threadIdx.x;
    int lane = tid & 31, wid = tid >> 5;
    int g = lane >> 2, l4 = lane & 3;
    int wm = wid >> 2, wn = wid & 3;    // wm: 2x32 rows(c), wn: 4x32 cols(dd)

    int sc  = tid >> 2;                 // staged channel / dd0 (0..63)
    int kf  = (tid & 3) << 2;           // k offset 0,4,8,12
    const float* Qp  = g_q  + ((long)b*256 + h*64 + sc) * HWn;
    const float* Kp0 = g_kv + ((long)b*512       + h*64 + sc) * HWn;       // dd = sc (tex)
    const float* Kp1 = g_kv + ((long)(b+16)*512  + h*64 + sc) * HWn;       // dd = sc+64 (dep)

    float acc[2][4][4];
    #pragma unroll
    for (int i = 0; i < 2; i++)
        #pragma unroll
        for (int j = 0; j < 4; j++)
            #pragma unroll
            for (int r = 0; r < 4; r++) acc[i][j][r] = 0.f;
    float qn = 0.f, kn0 = 0.f, kn1 = 0.f;
    int n0 = slab * 512;
    int kp = kf >> 1;

    for (int nc = n0; nc < n0 + 512; nc += 16) {
        {
            float4 v = *(const float4*)(Qp + nc + kf);
            qn += v.x*v.x + v.y*v.y + v.z*v.z + v.w*v.w;
            unsigned h0,l0,h1,l1;
            split2(v.x,v.y,h0,l0); split2(v.z,v.w,h1,l1);
            Qh[kp][sc]=h0; Ql[kp][sc]=l0; Qh[kp+1][sc]=h1; Ql[kp+1][sc]=l1;
        }
        {
            float4 v = *(const float4*)(Kp0 + nc + kf);
            kn0 += v.x*v.x + v.y*v.y + v.z*v.z + v.w*v.w;
            unsigned h0,l0,h1,l1;
            split2(v.x,v.y,h0,l0); split2(v.z,v.w,h1,l1);
            Kh[kp][sc]=h0; Kl[kp][sc]=l0; Kh[kp+1][sc]=h1; Kl[kp+1][sc]=l1;
        }
        {
            float4 v = *(const float4*)(Kp1 + nc + kf);
            kn1 += v.x*v.x + v.y*v.y + v.z*v.z + v.w*v.w;
            unsigned h0,l0,h1,l1;
            split2(v.x,v.y,h0,l0); split2(v.z,v.w,h1,l1);
            Kh[kp][sc+64]=h0; Kl[kp][sc+64]=l0; Kh[kp+1][sc+64]=h1; Kl[kp+1][sc+64]=l1;
        }
        __syncthreads();
        unsigned a_h[2][4], a_l[2][4];
        #pragma unroll
        for (int i = 0; i < 2; i++) {
            int row = wm*32 + i*16 + g;
            a_h[i][0]=Qh[l4][row];   a_h[i][1]=Qh[l4][row+8];
            a_h[i][2]=Qh[l4+4][row]; a_h[i][3]=Qh[l4+4][row+8];
            a_l[i][0]=Ql[l4][row];   a_l[i][1]=Ql[l4][row+8];
            a_l[i][2]=Ql[l4+4][row]; a_l[i][3]=Ql[l4+4][row+8];
        }
        #pragma unroll
        for (int j = 0; j < 4; j++) {
            int col = wn*32 + j*8 + g;
            unsigned bh0=Kh[l4][col], bh1=Kh[l4+4][col];
            unsigned bl0=Kl[l4][col], bl1=Kl[l4+4][col];
            #pragma unroll
            for (int i = 0; i < 2; i++) {
                mma_bf16(acc[i][j], a_h[i], bh0, bh1);
                mma_bf16(acc[i][j], a_l[i], bh0, bh1);
                mma_bf16(acc[i][j], a_h[i], bl0, bl1);
            }
        }
        __syncthreads();
    }
    long base = (long)slab*64 + bh;
    float* Sp = g_S + base*64*128;
    #pragma unroll
    for (int i = 0; i < 2; i++)
        #pragma unroll
        for (int h2 = 0; h2 < 2; h2++) {
            int row = wm*32 + i*16 + g + h2*8;
            #pragma unroll
            for (int j = 0; j < 4; j++) {
                int col = wn*32 + j*8 + 2*l4;
                *(float2*)&Sp[row*128 + col] = make_float2(acc[i][j][h2*2], acc[i][j][h2*2+1]);
            }
        }
    // quad-reduce the per-thread norm partials (4 kf-threads per sc)
    qn  += __shfl_xor_sync(0xffffffffu, qn, 1);  qn  += __shfl_xor_sync(0xffffffffu, qn, 2);
    kn0 += __shfl_xor_sync(0xffffffffu, kn0, 1); kn0 += __shfl_xor_sync(0xffffffffu, kn0, 2);
    kn1 += __shfl_xor_sync(0xffffffffu, kn1, 1); kn1 += __shfl_xor_sync(0xffffffffu, kn1, 2);
    if ((tid & 3) == 0) {
        g_qn2[base*64  + sc]      = qn;
        g_kn2[base*128 + sc]      = kn0;
        g_kn2[base*128 + sc + 64] = kn1;
    }
}

// ---------------- attention A2: combine partials, normalize, softmax, fold gate ----------------
__global__ void __launch_bounds__(128) attn_softmax(const float* __restrict__ attn_scale)
{
    int bh = blockIdx.x; int h = bh & 3;
    __shared__ float qn[64], kn[128];
    int tid = threadIdx.x;
    if (tid < 64) {
        float s = 0.f;
        for (int sl = 0; sl < NSPL; sl++) s += g_qn2[((long)sl*64 + bh)*64 + tid];
        qn[tid] = fmaxf(sqrtf(s), 1e-12f);
    }
    {
        float s = 0.f;
        for (int sl = 0; sl < NSPL; sl++) s += g_kn2[((long)sl*64 + bh)*128 + tid];
        kn[tid] = fmaxf(sqrtf(s), 1e-12f);
    }
    __syncthreads();
    int c = tid & 63, half = tid >> 6;
    float v[64];
    const float* Sp = g_S + (long)bh*64*128 + c*128 + half*64;
    float iq = 1.0f / qn[c];
    #pragma unroll
    for (int d = 0; d < 64; d++) {
        float s = 0.f;
        for (int sl = 0; sl < NSPL; sl++) s += Sp[(long)sl*64*64*128 + d];
        v[d] = s * iq / kn[half*64 + d];
    }
    float mx = -1e30f;
    #pragma unroll
    for (int d = 0; d < 64; d++) mx = fmaxf(mx, v[d]);
    float sum = 0.f;
    #pragma unroll
    for (int d = 0; d < 64; d++) { v[d] = expf(v[d] - mx); sum += v[d]; }
    float gg  = 1.0f / (1.0f + expf(-attn_scale[h]));
    float fac = (half == 0 ? gg : 1.0f - gg) / sum;
    float* P = g_P + (long)bh*64*128 + c*128 + half*64;
    #pragma unroll
    for (int d = 0; d < 64; d++) P[d] = v[d] * fac;
}

// ---------------- attention A3: O = P_comb(64x128) * [Vtex;Vdep](128xHW) ----------------
__global__ void __launch_bounds__(256) attn_pv()
{
    int nt = blockIdx.x;   // 0..31 (128 cols each)
    int bh = blockIdx.y;
    int b = bh >> 2, h = bh & 3;
    __shared__ unsigned Ph[64][72], Pl[64][72];   // all 64 k-pairs of P
    __shared__ unsigned Vh[8][136], Vl[8][136];   // one 16-dd chunk of V
    int tid = threadIdx.x;
    int lane = tid & 31, wid = tid >> 5;
    int g = lane >> 2, l4 = lane & 3;
    int wm = wid >> 2, wn = wid & 3;

    // ---- stage P (64 x 128) once; distinct c per lane -> conflict-free stores ----
    const float* P = g_P + (long)bh*64*128;
    #pragma unroll
    for (int q = 0; q < 8; q++) {
        int qi = tid + 256*q;
        int c  = qi & 63;
        int df = (qi >> 6) << 2;       // 0,4,...,124
        float4 v = *(const float4*)(P + c*128 + df);
        unsigned h0,l0,h1,l1;
        split2(v.x,v.y,h0,l0); split2(v.z,v.w,h1,l1);
        int kp = df >> 1;
        Ph[kp][c]=h0; Pl[kp][c]=l0; Ph[kp+1][c]=h1; Pl[kp+1][c]=l1;
    }
    int vkp = tid >> 5, vng = (tid & 31) << 2;
    int n0 = nt * 128;
    float acc[2][4][4];
    #pragma unroll
    for (int i = 0; i < 2; i++)
        #pragma unroll
        for (int j = 0; j < 4; j++)
            #pragma unroll
            for (int r = 0; r < 4; r++) acc[i][j][r] = 0.f;
    __syncthreads();

    for (int d0 = 0; d0 < 128; d0 += 16) {
        int dd = d0 + 2*vkp;   // even; dd and dd+1 in same region
        const float* vp = (dd < 64)
            ? g_kv + ((long)b*512      + 256 + h*64 + dd       )*HWn
            : g_kv + ((long)(b+16)*512 + 256 + h*64 + (dd - 64))*HWn;
        float4 r0 = *(const float4*)(vp + n0 + vng);
        float4 r1 = *(const float4*)(vp + HWn + n0 + vng);
        unsigned h0,l0,h1,l1,h2,l2,h3,l3;
        split2(r0.x, r1.x, h0, l0);
        split2(r0.y, r1.y, h1, l1);
        split2(r0.z, r1.z, h2, l2);
        split2(r0.w, r1.w, h3, l3);
        *(uint4*)&Vh[vkp][vng] = make_uint4(h0,h1,h2,h3);
        *(uint4*)&Vl[vkp][vng] = make_uint4(l0,l1,l2,l3);
        __syncthreads();
        int kb = d0 >> 1;
        unsigned a_h[2][4], a_l[2][4];
        #pragma unroll
        for (int i = 0; i < 2; i++) {
            int row = wm*32 + i*16 + g;
            a_h[i][0]=Ph[kb+l4][row];   a_h[i][1]=Ph[kb+l4][row+8];
            a_h[i][2]=Ph[kb+l4+4][row]; a_h[i][3]=Ph[kb+l4+4][row+8];
            a_l[i][0]=Pl[kb+l4][row];   a_l[i][1]=Pl[kb+l4][row+8];
            a_l[i][2]=Pl[kb+l4+4][row]; a_l[i][3]=Pl[kb+l4+4][row+8];
        }
        #pragma unroll
        for (int j = 0; j < 4; j++) {
            int col = wn*32 + j*8 + g;
            unsigned bh0=Vh[l4][col], bh1=Vh[l4+4][col];
            unsigned bl0=Vl[l4][col], bl1=Vl[l4+4][col];
            #pragma unroll
            for (int i = 0; i < 2; i++) {
                mma_bf16(acc[i][j], a_h[i], bh0, bh1);
                mma_bf16(acc[i][j], a_l[i], bh0, bh1);
                mma_bf16(acc[i][j], a_h[i], bl0, bl1);
            }
        }
        __syncthreads();
    }
    float* O = g_attn + ((long)b*256 + h*64) * HWn;
    #pragma unroll
    for (int i = 0; i < 2; i++)
        #pragma unroll
        for (int h2 = 0; h2 < 2; h2++) {
            int row = wm*32 + i*16 + g + h2*8;
            #pragma unroll
            for (int j = 0; j < 4; j++) {
                int col = wn*32 + j*8 + 2*l4;
                *(float2*)(O + (long)row*HWn + n0 + col) =
                    make_float2(acc[i][j][h2*2], acc[i][j][h2*2+1]);
            }
        }
}

// ---------------- depthwise 3x3 SAME + exact GELU ----------------
__global__ void dwconv_gelu(const float* __restrict__ dww)
{
    int bc = blockIdx.x;         // b*256 + c
    int c  = bc & 255;
    int hh = blockIdx.y * 4 + threadIdx.y;
    int tx = threadIdx.x;        // w in 0..63
    const float* in = g_y1 + (long)bc * HWn;
    float s = 0.f;
    #pragma unroll
    for (int di = -1; di <= 1; di++) {
        int hi = hh + di;
        if (hi < 0 || hi > 63) continue;
        #pragma unroll
        for (int dj = -1; dj <= 1; dj++) {
            int wj = tx + dj;
            if (wj < 0 || wj > 63) continue;
            s = fmaf(in[hi*64 + wj], dww[c*9 + (di+1)*3 + (dj+1)], s);
        }
    }
    float g = 0.5f * s * (1.0f + erff(s * 0.70710678118654752f));
    g_y2[(long)bc * HWn + hh*64 + tx] = g;
}

// ---------------- launch ----------------
extern "C" void kernel_launch(void* const* d_in, const int* in_sizes, int n_in,
                              void* d_out, int out_size)
{
    const float* img    = (const float*)d_in[0];
    const float* tex    = (const float*)d_in[1];
    const float* dep    = (const float*)d_in[2];
    const float* qnw    = (const float*)d_in[3];
    const float* qnb    = (const float*)d_in[4];
    const float* kvnw   = (const float*)d_in[5];
    const float* kvnb   = (const float*)d_in[6];
    const float* ascale = (const float*)d_in[7];
    const float* qpw    = (const float*)d_in[8];
    const float* kvpw   = (const float*)d_in[9];
    const float* opw    = (const float*)d_in[10];
    const float* opb    = (const float*)d_in[11];
    const float* fnw    = (const float*)d_in[12];
    const float* fnb    = (const float*)d_in[13];
    const float* f1w    = (const float*)d_in[14];
    const float* dww    = (const float*)d_in[15];
    const float* f2w    = (const float*)d_in[16];
    float* outp = (float*)d_out;

    float *p_q,*p_kv,*p_attn,*p_x,*p_y1,*p_y2;
    float *p_muq,*p_rsq,*p_mukv,*p_rskv,*p_mux,*p_rsx;
    float *p_Wq,*p_Sq,*p_Bq,*p_Wkv,*p_Skv,*p_Bkv,*p_Wf1,*p_Sf1,*p_Bf1;
    cudaGetSymbolAddress((void**)&p_q,    g_q);
    cudaGetSymbolAddress((void**)&p_kv,   g_kv);
    cudaGetSymbolAddress((void**)&p_attn, g_attn);
    cudaGetSymbolAddress((void**)&p_x,    g_x);
    cudaGetSymbolAddress((void**)&p_y1,   g_y1);
    cudaGetSymbolAddress((void**)&p_y2,   g_y2);
    cudaGetSymbolAddress((void**)&p_muq,  g_muq);
    cudaGetSymbolAddress((void**)&p_rsq,  g_rsq);
    cudaGetSymbolAddress((void**)&p_mukv, g_mukv);
    cudaGetSymbolAddress((void**)&p_rskv, g_rskv);
    cudaGetSymbolAddress((void**)&p_mux,  g_mux);
    cudaGetSymbolAddress((void**)&p_rsx,  g_rsx);
    cudaGetSymbolAddress((void**)&p_Wq,   g_Wq);
    cudaGetSymbolAddress((void**)&p_Sq,   g_Sq);
    cudaGetSymbolAddress((void**)&p_Bq,   g_Bq);
    cudaGetSymbolAddress((void**)&p_Wkv,  g_Wkv);
    cudaGetSymbolAddress((void**)&p_Skv,  g_Skv);
    cudaGetSymbolAddress((void**)&p_Bkv,  g_Bkv);
    cudaGetSymbolAddress((void**)&p_Wf1,  g_Wf1);
    cudaGetSymbolAddress((void**)&p_Sf1,  g_Sf1);
    cudaGetSymbolAddress((void**)&p_Bf1,  g_Bf1);

    // 0) fold LN weights into GEMM weights
    prep_w<<<1024, 256>>>(qpw,qnw,qnb, kvpw,kvnw,kvnb, f1w,fnw,fnb);
    // 1) LN stats
    ln_stats<<<1024, 256>>>(img, p_muq,  p_rsq);
    ln_stats<<<1024, 256>>>(tex, p_mukv, p_rskv);
    ln_stats<<<1024, 256>>>(dep, p_mukv + 65536, p_rskv + 65536);
    // 2) q = Wq' @ img  (LN folded in epilogue)
    gemm_tc<<<dim3(32,2,16), 256>>>(p_Wq, img, img, 99, CHW, p_q, CHW,
                                    p_muq, p_rsq, p_Sq, p_Bq, nullptr, nullptr, 0);
    // 3) kv = Wkv' @ [tex;dep]
    gemm_tc<<<dim3(32,4,32), 256>>>(p_Wkv, tex, dep, 16, CHW, p_kv, 512L*HWn,
                                    p_mukv, p_rskv, p_Skv, p_Bkv, nullptr, nullptr, 0);
    // 4) attention
    attn_scores <<<dim3(NSPL,64), 256>>>();
    attn_softmax<<<64, 128>>>(ascale);
    attn_pv     <<<dim3(32,64), 256>>>();
    // 5) x = img + Wo @ attn + bias
    gemm_tc<<<dim3(32,2,16), 256>>>(opw, p_attn, p_attn, 99, CHW, p_x, CHW,
                                    nullptr, nullptr, nullptr, nullptr, opb, img, CHW);
    // 6) ffn
    ln_stats<<<1024, 256>>>(p_x, p_mux, p_rsx);
    gemm_tc<<<dim3(32,2,16), 256>>>(p_Wf1, p_x, p_x, 99, CHW, p_y1, CHW,
                                    p_mux, p_rsx, p_Sf1, p_Bf1, nullptr, nullptr, 0);
    dwconv_gelu<<<dim3(4096,16), dim3(64,4)>>>(dww);
    // 7) out = x + fc2 @ y2
    gemm_tc<<<dim3(32,2,16), 256>>>(f2w, p_y2, p_y2, 99, CHW, outp, CHW,
                                    nullptr, nullptr, nullptr, nullptr, nullptr, p_x, CHW);
}